// round 1
// baseline (speedup 1.0000x reference)
#include <cuda_runtime.h>

#define HSTEP 0.01f
#define FEPS  1e-12f

// ---- constant weight bank: 260 floats ----
__constant__ float cW[260];
#define OJw1 0
#define OJb1 40
#define OJw2 50
#define OJb2 110
#define OVw1 116
#define OVb1 156
#define OVw2 166
#define OVb2 176
#define Ogw1 177
#define Ogb1 217
#define Ogw2 227
#define Ogb2 257

// accurate-enough tanh: exact identity, __expf rel err ~1e-7
__device__ __forceinline__ float ftanh(float x) {
    float e = __expf(2.0f * x);
    float r = __fdividef(1.0f, e + 1.0f);   // e+1 in [1,inf): safe
    return 1.0f - 2.0f * r;
}

// grad of scalar V-MLP wrt q (analytic): dV = Vw1^T (Vw2 ⊙ (1 - tanh^2(Vw1 q + Vb1)))
__device__ __forceinline__ void vgrad(float q0, float q1, float q2, float q3,
                                      float& d0, float& d1, float& d2, float& d3) {
    d0 = d1 = d2 = d3 = 0.0f;
#pragma unroll
    for (int k = 0; k < 10; k++) {
        float w0 = cW[OVw1 + 4*k + 0];
        float w1 = cW[OVw1 + 4*k + 1];
        float w2 = cW[OVw1 + 4*k + 2];
        float w3 = cW[OVw1 + 4*k + 3];
        float z = cW[OVb1 + k] + w0*q0 + w1*q1 + w2*q2 + w3*q3;
        float t = ftanh(z);
        float c = cW[OVw2 + k] * (1.0f - t*t);
        d0 += c*w0; d1 += c*w1; d2 += c*w2; d3 += c*w3;
    }
}

__global__ void __launch_bounds__(256)
step_kernel(const float4* __restrict__ xin, float4* __restrict__ xout, int B) {
    int i = blockIdx.x * blockDim.x + threadIdx.x;
    if (i >= B) return;

    float4 a = xin[2*i];
    float4 b = xin[2*i + 1];
    float q0 = a.x, q1 = a.y, q2 = a.z, q3 = a.w;
    float w0 = b.x, w1 = b.y, w2 = b.z, u = b.w;

    // ---- J MLP -> l[6] ----
    float l[6];
    {
        float hd[10];
#pragma unroll
        for (int k = 0; k < 10; k++) {
            float z = cW[OJb1 + k]
                    + cW[OJw1 + 4*k + 0]*q0 + cW[OJw1 + 4*k + 1]*q1
                    + cW[OJw1 + 4*k + 2]*q2 + cW[OJw1 + 4*k + 3]*q3;
            hd[k] = ftanh(z);
        }
#pragma unroll
        for (int r = 0; r < 6; r++) {
            float s = cW[OJb2 + r];
#pragma unroll
            for (int k = 0; k < 10; k++) s += cW[OJw2 + 10*r + k] * hd[k];
            l[r] = s;
        }
    }

    // ---- M = L L^T + 0.01 I (symmetric), L = [[l0,0,0],[l1,l2,0],[l3,l4,l5]] ----
    float M00 = l[0]*l[0] + 0.01f;
    float M01 = l[0]*l[1];
    float M02 = l[0]*l[3];
    float M11 = l[1]*l[1] + l[2]*l[2] + 0.01f;
    float M12 = l[1]*l[3] + l[2]*l[4];
    float M22 = l[3]*l[3] + l[4]*l[4] + l[5]*l[5] + 0.01f;

    // ---- J = inv(M) via adjugate (symmetric) ----
    float c00 = M11*M22 - M12*M12;
    float c01 = M02*M12 - M01*M22;
    float c02 = M01*M12 - M02*M11;
    float c11 = M00*M22 - M02*M02;
    float c12 = M01*M02 - M00*M12;
    float c22 = M00*M11 - M01*M01;
    float det = M00*c00 + M01*c01 + M02*c02;
    float id  = 1.0f / det;                       // IEEE div: conditioning matters
    float J00 = c00*id, J01 = c01*id, J02 = c02*id;
    float J11 = c11*id, J12 = c12*id, J22 = c22*id;

    // ---- g MLP -> fk = (h/2) * u * g ----
    float fk0, fk1, fk2;
    {
        float hd[10];
#pragma unroll
        for (int k = 0; k < 10; k++) {
            float z = cW[Ogb1 + k]
                    + cW[Ogw1 + 4*k + 0]*q0 + cW[Ogw1 + 4*k + 1]*q1
                    + cW[Ogw1 + 4*k + 2]*q2 + cW[Ogw1 + 4*k + 3]*q3;
            hd[k] = ftanh(z);
        }
        float g[3];
#pragma unroll
        for (int r = 0; r < 3; r++) {
            float s = cW[Ogb2 + r];
#pragma unroll
            for (int k = 0; k < 10; k++) s += cW[Ogw2 + 10*r + k] * hd[k];
            g[r] = s;
        }
        float cu = HSTEP * u * 0.5f;
        fk0 = cu * g[0]; fk1 = cu * g[1]; fk2 = cu * g[2];
    }

    // ---- pk = 2 J w ----
    float pk0 = 2.0f*(J00*w0 + J01*w1 + J02*w2);
    float pk1 = 2.0f*(J01*w0 + J11*w1 + J12*w2);
    float pk2 = 2.0f*(J02*w0 + J12*w1 + J22*w2);

    // ---- dV at qk ----
    float dv0, dv1, dv2, dv3;
    vgrad(q0, q1, q2, q3, dv0, dv1, dv2, dv3);

    // ---- H(qk) dVk = qv*dv0 + q0*dv_v - qv x dv_v ----
    float Hd0 = q1*dv0 + q0*dv1 - (q2*dv3 - q3*dv2);
    float Hd1 = q2*dv0 + q0*dv2 - (q3*dv1 - q1*dv3);
    float Hd2 = q3*dv0 + q0*dv3 - (q1*dv2 - q2*dv1);

    // ---- RHS = -h/4 * (pk + fk - h/2 * Hd) ----
    float R0 = -0.0025f * (pk0 + fk0 - 0.005f*Hd0);
    float R1 = -0.0025f * (pk1 + fk1 - 0.005f*Hd1);
    float R2 = -0.0025f * (pk2 + fk2 - 0.005f*Hd2);

    // ---- Newton (4 iterations), analytic jacfwd of res(xi) ----
    float xi0 = 0.0f, xi1 = 0.0f, xi2 = 0.0f;
#pragma unroll
    for (int it = 0; it < 4; it++) {
        float s2  = xi0*xi0 + xi1*xi1 + xi2*xi2;
        bool  act = (s2 >= FEPS);                 // JAX maximum(s,EPS) grad gate
        float th  = sqrtf(act ? s2 : FEPS);
        float sn, cs;
        __sincosf(th, &sn, &cs);
        float ith  = __fdividef(1.0f, th);
        float sinc = sn * ith;
        float qv0 = -sinc*xi0, qv1 = -sinc*xi1, qv2 = -sinc*xi2;
        // m = J qv
        float m0 = J00*qv0 + J01*qv1 + J02*qv2;
        float m1 = J01*qv0 + J11*qv1 + J12*qv2;
        float m2 = J02*qv0 + J12*qv1 + J22*qv2;
        // res = cos*m - qv x m - RHS
        float r0 = cs*m0 - (qv1*m2 - qv2*m1) - R0;
        float r1 = cs*m1 - (qv2*m0 - qv0*m2) - R1;
        float r2 = cs*m2 - (qv0*m1 - qv1*m0) - R2;
        // jacobian columns
        float g0 = act ? xi0*ith : 0.0f;   // d theta / d xi
        float g1 = act ? xi1*ith : 0.0f;
        float g2 = act ? xi2*ith : 0.0f;
        float beta = (cs - sinc) * ith;    // d sinc / d theta
        float A[9];
#pragma unroll
        for (int k = 0; k < 3; k++) {
            float gk = (k == 0) ? g0 : ((k == 1) ? g1 : g2);
            float bk = beta * gk;
            float cA0 = -bk*xi0 - ((k == 0) ? sinc : 0.0f);   // dqv/dxi_k
            float cA1 = -bk*xi1 - ((k == 1) ? sinc : 0.0f);
            float cA2 = -bk*xi2 - ((k == 2) ? sinc : 0.0f);
            float dq0 = -sn * gk;                              // dq0/dxi_k
            float Jc0 = J00*cA0 + J01*cA1 + J02*cA2;
            float Jc1 = J01*cA0 + J11*cA1 + J12*cA2;
            float Jc2 = J02*cA0 + J12*cA1 + J22*cA2;
            A[0*3 + k] = dq0*m0 + cs*Jc0 - (cA1*m2 - cA2*m1) - (qv1*Jc2 - qv2*Jc1);
            A[1*3 + k] = dq0*m1 + cs*Jc1 - (cA2*m0 - cA0*m2) - (qv2*Jc0 - qv0*Jc2);
            A[2*3 + k] = dq0*m2 + cs*Jc2 - (cA0*m1 - cA1*m0) - (qv0*Jc1 - qv1*Jc0);
        }
        // Cramer solve A d = r  (columns u=A[:,0], v=A[:,1], t=A[:,2])
        float cvt0 = A[4]*A[8] - A[7]*A[5];   // v x t
        float cvt1 = A[7]*A[2] - A[1]*A[8];
        float cvt2 = A[1]*A[5] - A[4]*A[2];
        float ctu0 = A[5]*A[6] - A[8]*A[3];   // t x u
        float ctu1 = A[8]*A[0] - A[2]*A[6];
        float ctu2 = A[2]*A[3] - A[5]*A[0];
        float cuv0 = A[3]*A[7] - A[6]*A[4];   // u x v
        float cuv1 = A[6]*A[1] - A[0]*A[7];
        float cuv2 = A[0]*A[4] - A[3]*A[1];
        float dt  = A[0]*cvt0 + A[3]*cvt1 + A[6]*cvt2;
        float idt = 1.0f / dt;
        xi0 -= (r0*cvt0 + r1*cvt1 + r2*cvt2) * idt;
        xi1 -= (r0*ctu0 + r1*ctu1 + r2*ctu2) * idt;
        xi2 -= (r0*cuv0 + r1*cuv1 + r2*cuv2) * idt;
    }

    // ---- e = quat_exp(xi) ----
    float s2 = xi0*xi0 + xi1*xi1 + xi2*xi2;
    float th = sqrtf(fmaxf(s2, FEPS));
    float sn, cs;
    __sincosf(th, &sn, &cs);
    float sinc = __fdividef(sn, th);
    float e0 = cs, e1 = xi0*sinc, e2 = xi1*sinc, e3 = xi2*sinc;

    // ---- qk_next = quat_mul(qk, e) ----
    float qn0 = q0*e0 - q1*e1 - q2*e2 - q3*e3;
    float qn1 = q0*e1 + q1*e0 + q2*e3 - q3*e2;
    float qn2 = q0*e2 - q1*e3 + q2*e0 + q3*e1;
    float qn3 = q0*e3 + q1*e2 - q2*e1 + q3*e0;

    // ---- dV at qk_next ----
    float dn0, dn1, dn2, dn3;
    vgrad(qn0, qn1, qn2, qn3, dn0, dn1, dn2, dn3);

    // ---- qq = quat_mul(conj(qk), qk_next) ----
    float p0 = q0, p1 = -q1, p2 = -q2, p3 = -q3;
    float qq0 = p0*qn0 - p1*qn1 - p2*qn2 - p3*qn3;
    float qq1 = p0*qn1 + p1*qn0 + p2*qn3 - p3*qn2;
    float qq2 = p0*qn2 - p1*qn3 + p2*qn0 + p3*qn1;
    float qq3 = p0*qn3 + p1*qn2 - p2*qn1 + p3*qn0;

    // ---- y = J qq_v ; Gqq y = qq0*y - qq_v x y ----
    float y0 = J00*qq1 + J01*qq2 + J02*qq3;
    float y1 = J01*qq1 + J11*qq2 + J12*qq3;
    float y2 = J02*qq1 + J12*qq2 + J22*qq3;
    float G0 = qq0*y0 - (qq2*y2 - qq3*y1);
    float G1 = qq0*y1 - (qq3*y0 - qq1*y2);
    float G2 = qq0*y2 - (qq1*y1 - qq2*y0);

    // ---- H(qk_next) dVn ----
    float Hn0 = qn1*dn0 + qn0*dn1 - (qn2*dn3 - qn3*dn2);
    float Hn1 = qn2*dn0 + qn0*dn2 - (qn3*dn1 - qn1*dn3);
    float Hn2 = qn3*dn0 + qn0*dn3 - (qn1*dn2 - qn2*dn1);

    // ---- pk_next = (4/h) Gqq y - (h/2) Hn + fk ; wk_next = 0.5 M pk_next ----
    float pn0 = 400.0f*G0 - 0.005f*Hn0 + fk0;
    float pn1 = 400.0f*G1 - 0.005f*Hn1 + fk1;
    float pn2 = 400.0f*G2 - 0.005f*Hn2 + fk2;
    float wn0 = 0.5f*(M00*pn0 + M01*pn1 + M02*pn2);
    float wn1 = 0.5f*(M01*pn0 + M11*pn1 + M12*pn2);
    float wn2 = 0.5f*(M02*pn0 + M12*pn1 + M22*pn2);

    xout[2*i]     = make_float4(qn0, qn1, qn2, qn3);
    xout[2*i + 1] = make_float4(wn0, wn1, wn2, u);
}

extern "C" void kernel_launch(void* const* d_in, const int* in_sizes, int n_in,
                              void* d_out, int out_size) {
    // weights -> constant bank (D2D async copies: graph-capturable memcpy nodes)
    cudaMemcpyToSymbolAsync(cW, d_in[1],  160, 0,    cudaMemcpyDeviceToDevice, 0); // Jw1
    cudaMemcpyToSymbolAsync(cW, d_in[2],  40,  160,  cudaMemcpyDeviceToDevice, 0); // Jb1
    cudaMemcpyToSymbolAsync(cW, d_in[3],  240, 200,  cudaMemcpyDeviceToDevice, 0); // Jw2
    cudaMemcpyToSymbolAsync(cW, d_in[4],  24,  440,  cudaMemcpyDeviceToDevice, 0); // Jb2
    cudaMemcpyToSymbolAsync(cW, d_in[5],  160, 464,  cudaMemcpyDeviceToDevice, 0); // Vw1
    cudaMemcpyToSymbolAsync(cW, d_in[6],  40,  624,  cudaMemcpyDeviceToDevice, 0); // Vb1
    cudaMemcpyToSymbolAsync(cW, d_in[7],  40,  664,  cudaMemcpyDeviceToDevice, 0); // Vw2
    cudaMemcpyToSymbolAsync(cW, d_in[8],  4,   704,  cudaMemcpyDeviceToDevice, 0); // Vb2
    cudaMemcpyToSymbolAsync(cW, d_in[9],  160, 708,  cudaMemcpyDeviceToDevice, 0); // gw1
    cudaMemcpyToSymbolAsync(cW, d_in[10], 40,  868,  cudaMemcpyDeviceToDevice, 0); // gb1
    cudaMemcpyToSymbolAsync(cW, d_in[11], 120, 908,  cudaMemcpyDeviceToDevice, 0); // gw2
    cudaMemcpyToSymbolAsync(cW, d_in[12], 12,  1028, cudaMemcpyDeviceToDevice, 0); // gb2

    int B = in_sizes[0] / 8;
    step_kernel<<<(B + 255) / 256, 256>>>((const float4*)d_in[0], (float4*)d_out, B);
}